// round 7
// baseline (speedup 1.0000x reference)
#include <cuda_runtime.h>

#define NROWS 65536   // N_TOKENS * BATCH
#define FDIM  256     // HW
#define MDIM  1024    // MEM_DIM

// ---------------- scratch (static device globals; no allocation) ----------------
__device__ float g_q[NROWS * FDIM];             // raw q, row-major [N, F]        (64 MB)
__device__ float g_qm[NROWS];
__device__ float g_qv[NROWS];
__device__ float g_kcT[FDIM * MDIM];            // centered k, TRANSPOSED [F, M]  (1 MB)
__device__ float g_vmat[MDIM * FDIM];           // v, row-major [M, F]            (1 MB)
__device__ float g_km[MDIM];
__device__ float g_kv[MDIM];
__device__ float g_S[(size_t)NROWS * MDIM];     // p = exp(ssim) [N, M]           (256 MB)
__device__ float g_psum[8 * NROWS];             // per-m-block partial row sums   (2 MB)

// ---------------- packed f32x2 helpers (full-rate FP32 on sm_103a) --------------
__device__ __forceinline__ unsigned long long pk2(float lo, float hi) {
    unsigned long long r;
    asm("mov.b64 %0, {%1, %2};" : "=l"(r) : "f"(lo), "f"(hi));
    return r;
}
__device__ __forceinline__ void fma2(unsigned long long& d, unsigned long long a,
                                     unsigned long long b) {
    asm("fma.rn.f32x2 %0, %1, %2, %0;" : "+l"(d) : "l"(a), "l"(b));
}
__device__ __forceinline__ float2 upk2(unsigned long long v) {
    float2 r;
    asm("mov.b64 {%0, %1}, %2;" : "=f"(r.x), "=f"(r.y) : "l"(v));
    return r;
}

// ---------------- cp.async helpers ----------------------------------------------
__device__ __forceinline__ void cpa16(void* dst, const void* src) {
    unsigned saddr = (unsigned)__cvta_generic_to_shared(dst);
    asm volatile("cp.async.cg.shared.global [%0], [%1], 16;" ::"r"(saddr), "l"(src));
}
__device__ __forceinline__ void cpa_commit() {
    asm volatile("cp.async.commit_group;" ::: "memory");
}
template <int N>
__device__ __forceinline__ void cpa_wait() {
    asm volatile("cp.async.wait_group %0;" ::"n"(N) : "memory");
}

// =================================================================================
// rowgemm: C[64 x 256] = A_tile @ W^T   (W is [256,256] row-major)
// MODE 0: q  -> row stats (mean/var), RAW rows to g_q, g_qm/g_qv
// MODE 1: k  -> row stats, centered TRANSPOSED to g_kcT, g_km/g_kv
// MODE 2: v  -> plain row-major store to g_vmat
// =================================================================================
template <int MODE>
__global__ __launch_bounds__(256, 2) void rowgemm_kernel(const float* __restrict__ A,
                                                         const float* __restrict__ W) {
    __shared__ float As[16][68];    // As[kk][row]
    __shared__ float Bs[16][260];   // Bs[kk][col]

    const int tid = threadIdx.x;
    const int n0  = blockIdx.x * 64;
    const int tr  = tid >> 5;   // 0..7
    const int tc  = tid & 31;   // 0..31

    unsigned long long accp[8][4];
#pragma unroll
    for (int i = 0; i < 8; i++)
#pragma unroll
        for (int j = 0; j < 4; j++) accp[i][j] = 0ull;

    for (int k0 = 0; k0 < 256; k0 += 16) {
        {   // A tile 64x16 (transpose into smem)
            int r = tid >> 2;
            int c = (tid & 3) << 2;
            float4 v = *(const float4*)&A[(n0 + r) * 256 + k0 + c];
            As[c + 0][r] = v.x; As[c + 1][r] = v.y; As[c + 2][r] = v.z; As[c + 3][r] = v.w;
        }
#pragma unroll
        for (int it = 0; it < 4; it++) {   // W tile 256x16 (transpose into smem)
            int fid = tid + (it << 8);
            int j = fid >> 2;
            int c = (fid & 3) << 2;
            float4 v = *(const float4*)&W[j * 256 + k0 + c];
            Bs[c + 0][j] = v.x; Bs[c + 1][j] = v.y; Bs[c + 2][j] = v.z; Bs[c + 3][j] = v.w;
        }
        __syncthreads();
#pragma unroll
        for (int kk = 0; kk < 16; kk++) {
            float4 a0 = *(const float4*)&As[kk][tr * 4];
            float4 a1 = *(const float4*)&As[kk][32 + tr * 4];
            ulonglong2 b0 = *(const ulonglong2*)(const void*)&Bs[kk][tc * 4];
            ulonglong2 b1 = *(const ulonglong2*)(const void*)&Bs[kk][128 + tc * 4];
            unsigned long long ap[8] = {pk2(a0.x, a0.x), pk2(a0.y, a0.y), pk2(a0.z, a0.z),
                                        pk2(a0.w, a0.w), pk2(a1.x, a1.x), pk2(a1.y, a1.y),
                                        pk2(a1.z, a1.z), pk2(a1.w, a1.w)};
            unsigned long long bv[4] = {b0.x, b0.y, b1.x, b1.y};
#pragma unroll
            for (int i = 0; i < 8; i++)
#pragma unroll
                for (int j = 0; j < 4; j++) fma2(accp[i][j], ap[i], bv[j]);
        }
        __syncthreads();
    }

    float acc[8][8];
#pragma unroll
    for (int i = 0; i < 8; i++)
#pragma unroll
        for (int j2 = 0; j2 < 4; j2++) {
            float2 u = upk2(accp[i][j2]);
            acc[i][2 * j2 + 0] = u.x;
            acc[i][2 * j2 + 1] = u.y;
        }

#pragma unroll
    for (int i = 0; i < 8; i++) {
        const int row = n0 + tr * 4 + (i & 3) + ((i >> 2) << 5);
        if (MODE == 2) {
            *(float4*)&g_vmat[row * 256 + tc * 4] =
                make_float4(acc[i][0], acc[i][1], acc[i][2], acc[i][3]);
            *(float4*)&g_vmat[row * 256 + 128 + tc * 4] =
                make_float4(acc[i][4], acc[i][5], acc[i][6], acc[i][7]);
        } else {
            float s = 0.f, ss = 0.f;
#pragma unroll
            for (int j = 0; j < 8; j++) { s += acc[i][j]; ss += acc[i][j] * acc[i][j]; }
#pragma unroll
            for (int o = 16; o > 0; o >>= 1) {
                s  += __shfl_xor_sync(0xffffffffu, s, o);
                ss += __shfl_xor_sync(0xffffffffu, ss, o);
            }
            const float mean = s * (1.0f / 256.0f);
            const float var  = (ss - 256.0f * mean * mean) * (1.0f / 255.0f);
            if (MODE == 0) {
                if (tc == 0) { g_qm[row] = mean; g_qv[row] = var; }
                // store RAW q: cov = q . kcT is exact since sum(kcT row) == 0
                *(float4*)&g_q[row * 256 + tc * 4] =
                    make_float4(acc[i][0], acc[i][1], acc[i][2], acc[i][3]);
                *(float4*)&g_q[row * 256 + 128 + tc * 4] =
                    make_float4(acc[i][4], acc[i][5], acc[i][6], acc[i][7]);
            } else {   // MODE 1: k -> centered transposed
                if (tc == 0) { g_km[row] = mean; g_kv[row] = var; }
#pragma unroll
                for (int j = 0; j < 8; j++) {
                    const int col = tc * 4 + (j & 3) + ((j >> 2) << 7);
                    g_kcT[col * 1024 + row] = acc[i][j] - mean;
                }
            }
        }
    }
}

// =================================================================================
// Shared 128x128x(BK=32) cp.async double-buffered GEMM core.
// A in smem ROW-MAJOR [128][36] (pad 36 for banks + 16B rows), B [32][132].
// Thread (tr=tid>>4, tc=tid&15): rows tr*4+i (+64), cols tc*4+j (+64).
// =================================================================================
#define A_STR 36
#define B_STR 132
#define A_BUF (128 * A_STR)          // 4608 floats
#define B_BUF (32 * B_STR)           // 4224 floats
#define SMEM_FLOATS (2 * A_BUF + 2 * B_BUF)
#define SMEM_BYTES (SMEM_FLOATS * 4) // 70656

__device__ __forceinline__ void tile_load(float* As, float* Bs, int tid,
                                          const float* __restrict__ Agl, int a_ld,
                                          const float* __restrict__ Bgl, int b_ld) {
#pragma unroll
    for (int it = 0; it < 4; it++) {   // A: 128 rows x 32 floats
        int ch = tid + (it << 8);
        int r = ch >> 3, cp = (ch & 7) << 2;
        cpa16(&As[r * A_STR + cp], &Agl[(size_t)r * a_ld + cp]);
    }
#pragma unroll
    for (int it = 0; it < 4; it++) {   // B: 32 rows x 128 floats (verbatim)
        int ch = tid + (it << 8);
        int rr = ch >> 5, cc = (ch & 31) << 2;
        cpa16(&Bs[rr * B_STR + cc], &Bgl[(size_t)rr * b_ld + cc]);
    }
    cpa_commit();
}

__device__ __forceinline__ void tile_mma(const float* __restrict__ As,
                                         const float* __restrict__ Bs, int tr, int tc,
                                         unsigned long long accp[8][4]) {
#pragma unroll
    for (int kk = 0; kk < 32; kk++) {
        const float* a = As + kk;
        float s0 = a[(tr * 4 + 0) * A_STR], s1 = a[(tr * 4 + 1) * A_STR];
        float s2 = a[(tr * 4 + 2) * A_STR], s3 = a[(tr * 4 + 3) * A_STR];
        float s4 = a[(64 + tr * 4 + 0) * A_STR], s5 = a[(64 + tr * 4 + 1) * A_STR];
        float s6 = a[(64 + tr * 4 + 2) * A_STR], s7 = a[(64 + tr * 4 + 3) * A_STR];
        ulonglong2 b0 = *(const ulonglong2*)(const void*)&Bs[kk * B_STR + tc * 4];
        ulonglong2 b1 = *(const ulonglong2*)(const void*)&Bs[kk * B_STR + 64 + tc * 4];
        unsigned long long ap[8] = {pk2(s0, s0), pk2(s1, s1), pk2(s2, s2), pk2(s3, s3),
                                    pk2(s4, s4), pk2(s5, s5), pk2(s6, s6), pk2(s7, s7)};
        unsigned long long bv[4] = {b0.x, b0.y, b1.x, b1.y};
#pragma unroll
        for (int i = 0; i < 8; i++)
#pragma unroll
            for (int j = 0; j < 4; j++) fma2(accp[i][j], ap[i], bv[j]);
    }
}

// =================================================================================
// ssim: P[N, M] = exp(ssim(q, k));  cov = q @ kcT / 255 (q raw: mean term vanishes)
// also writes deterministic per-m-block row-sum partials to g_psum.
// =================================================================================
__global__ __launch_bounds__(256, 2) void ssim_kernel() {
    extern __shared__ float sm[];
    float* As[2] = {sm, sm + A_BUF};
    float* Bs[2] = {sm + 2 * A_BUF, sm + 2 * A_BUF + B_BUF};

    const int tid = threadIdx.x;
    const int n0 = blockIdx.y << 7;
    const int m0 = blockIdx.x << 7;
    const int tr = tid >> 4;
    const int tc = tid & 15;

    unsigned long long accp[8][4];
#pragma unroll
    for (int i = 0; i < 8; i++)
#pragma unroll
        for (int j = 0; j < 4; j++) accp[i][j] = 0ull;

    tile_load(As[0], Bs[0], tid, &g_q[(size_t)n0 * 256], 256, &g_kcT[m0], 1024);

#pragma unroll 1
    for (int t = 0; t < 8; t++) {
        if (t + 1 < 8)
            tile_load(As[(t + 1) & 1], Bs[(t + 1) & 1], tid,
                      &g_q[(size_t)n0 * 256 + (t + 1) * 32], 256,
                      &g_kcT[(size_t)(t + 1) * 32 * 1024 + m0], 1024);
        if (t + 1 < 8) cpa_wait<1>(); else cpa_wait<0>();
        __syncthreads();
        tile_mma(As[t & 1], Bs[t & 1], tr, tc, accp);
        __syncthreads();
    }

    float acc[8][8];
#pragma unroll
    for (int i = 0; i < 8; i++)
#pragma unroll
        for (int j2 = 0; j2 < 4; j2++) {
            float2 u = upk2(accp[i][j2]);
            acc[i][2 * j2 + 0] = u.x;
            acc[i][2 * j2 + 1] = u.y;
        }

    const float C1f = 0.01f, C2f = 0.03f, EPSf = 1e-8f, INV255 = 1.0f / 255.0f;

    float qm[8], qv[8], km[8], kv[8];
#pragma unroll
    for (int i = 0; i < 8; i++) {
        const int row = n0 + tr * 4 + (i & 3) + ((i >> 2) << 6);
        qm[i] = g_qm[row];
        qv[i] = g_qv[row];
    }
#pragma unroll
    for (int j = 0; j < 8; j++) {
        const int col = m0 + tc * 4 + (j & 3) + ((j >> 2) << 6);
        km[j] = g_km[col];
        kv[j] = g_kv[col];
    }

#pragma unroll
    for (int i = 0; i < 8; i++) {
        const int row = n0 + tr * 4 + (i & 3) + ((i >> 2) << 6);
        float p[8], rowp = 0.f;
#pragma unroll
        for (int j = 0; j < 8; j++) {
            const float cov = acc[i][j] * INV255;
            const float num = (2.0f * qm[i] * km[j] + C1f) * (2.0f * cov + C2f);
            const float den =
                (qm[i] * qm[i] + km[j] * km[j] + C1f) * (qv[i] + kv[j] + C2f) + EPSf;
            p[j] = __expf(num / den);     // ssim bounded ~[-1,1]: exp is safe w/o max
            rowp += p[j];
        }
        *(float4*)&g_S[(size_t)row * 1024 + m0 + tc * 4] =
            make_float4(p[0], p[1], p[2], p[3]);
        *(float4*)&g_S[(size_t)row * 1024 + m0 + 64 + tc * 4] =
            make_float4(p[4], p[5], p[6], p[7]);
        // reduce rowp over the 16 tc lanes (half-warp; lane = (tr&1)*16 + tc)
#pragma unroll
        for (int o = 8; o > 0; o >>= 1) rowp += __shfl_xor_sync(0xffffffffu, rowp, o);
        if (tc == 0) g_psum[blockIdx.x * NROWS + row] = rowp;   // deterministic partial
    }
}

// =================================================================================
// out = (P @ v) / rowsum :  [N,1024] x [1024,256] -> d_out.
// =================================================================================
__global__ __launch_bounds__(256, 2) void out_kernel(float* __restrict__ out) {
    extern __shared__ float sm[];
    float* As[2] = {sm, sm + A_BUF};
    float* Bs[2] = {sm + 2 * A_BUF, sm + 2 * A_BUF + B_BUF};

    const int tid = threadIdx.x;
    const int n0 = blockIdx.y << 7;
    const int j0 = blockIdx.x << 7;
    const int tr = tid >> 4;
    const int tc = tid & 15;

    unsigned long long accp[8][4];
#pragma unroll
    for (int i = 0; i < 8; i++)
#pragma unroll
        for (int j = 0; j < 4; j++) accp[i][j] = 0ull;

    tile_load(As[0], Bs[0], tid, &g_S[(size_t)n0 * 1024], 1024, &g_vmat[j0], 256);

#pragma unroll 1
    for (int t = 0; t < 32; t++) {
        if (t + 1 < 32)
            tile_load(As[(t + 1) & 1], Bs[(t + 1) & 1], tid,
                      &g_S[(size_t)n0 * 1024 + (t + 1) * 32], 1024,
                      &g_vmat[(size_t)(t + 1) * 32 * 256 + j0], 256);
        if (t + 1 < 32) cpa_wait<1>(); else cpa_wait<0>();
        __syncthreads();
        tile_mma(As[t & 1], Bs[t & 1], tr, tc, accp);
        __syncthreads();
    }

#pragma unroll
    for (int i = 0; i < 8; i++) {
        const int row = n0 + tr * 4 + (i & 3) + ((i >> 2) << 6);
        float s = 0.f;
#pragma unroll
        for (int b = 0; b < 8; b++) s += g_psum[b * NROWS + row];
        const float inv = 1.0f / s;
        float2 u0 = upk2(accp[i][0]);
        float2 u1 = upk2(accp[i][1]);
        float2 u2 = upk2(accp[i][2]);
        float2 u3 = upk2(accp[i][3]);
        *(float4*)&out[row * 256 + j0 + tc * 4] =
            make_float4(u0.x * inv, u0.y * inv, u1.x * inv, u1.y * inv);
        *(float4*)&out[row * 256 + j0 + 64 + tc * 4] =
            make_float4(u2.x * inv, u2.y * inv, u3.x * inv, u3.y * inv);
    }
}

// =================================================================================
extern "C" void kernel_launch(void* const* d_in, const int* in_sizes, int n_in,
                              void* d_out, int out_size) {
    (void)in_sizes; (void)n_in; (void)out_size;
    const float* x   = (const float*)d_in[0];   // [8192, 8, 256] -> [65536, 256]
    const float* mem = (const float*)d_in[1];   // [1024, 16, 16] -> [1024, 256]
    const float* Wq  = (const float*)d_in[2];   // [256, 256]
    const float* Wk  = (const float*)d_in[3];
    const float* Wv  = (const float*)d_in[4];
    float* out = (float*)d_out;

    cudaFuncSetAttribute(ssim_kernel, cudaFuncAttributeMaxDynamicSharedMemorySize,
                         SMEM_BYTES);
    cudaFuncSetAttribute(out_kernel, cudaFuncAttributeMaxDynamicSharedMemorySize,
                         SMEM_BYTES);

    rowgemm_kernel<1><<<16, 256>>>(mem, Wk);               // k -> centered kcT + km/kv
    rowgemm_kernel<2><<<16, 256>>>(mem, Wv);               // v
    rowgemm_kernel<0><<<1024, 256>>>(x, Wq);               // q raw + qm/qv
    ssim_kernel<<<dim3(8, 512), 256, SMEM_BYTES>>>();      // P = exp(ssim), psum
    out_kernel<<<dim3(2, 512), 256, SMEM_BYTES>>>(out);    // out = (P @ v)/rowsum
}